// round 13
// baseline (speedup 1.0000x reference)
#include <cuda_runtime.h>
#include <cuda_bf16.h>
#include <cstddef>
#include <cstdint>

#define NN    100000        // nodes
#define D1    128           // input / layer-2 output dim
#define D2    256           // hidden dim
#define EMAX  700000        // max edges (setup uses 600k)
#define NCHUNK ((NN + 1023) / 1024)

// -------- scratch (no allocation allowed; __device__ globals) --------
__device__ int   g_cnt[NN];             // in-edge counts (no self loop)
__device__ float g_dinv[NN];
__device__ int   g_off[NN + 1];         // CSR row offsets
__device__ int   g_cursor[NN];          // placement cursors
__device__ int   g_csum[NCHUNK];        // chunk sums for scan
__device__ int   g_csr[EMAX];           // CSR column (src) indices
__device__ float g_bufA[(size_t)NN * D1];   // agg1 (tf32-rounded), later h2 (f32)
__device__ float g_bufB[(size_t)NN * D2];   // out1 (post relu, tf32-rounded)
__device__ float g_W1t[D1 * D2];            // tf32-rounded weights
__device__ float g_W2t[D2 * D1];

__device__ __forceinline__ float f2tf32(float x) {
    unsigned u;
    asm("cvt.rna.tf32.f32 %0, %1;" : "=r"(u) : "f"(x));
    return __uint_as_float(u);
}

__device__ __forceinline__ void cp_async16(uint32_t smem, const void* gmem, int szbytes) {
    asm volatile("cp.async.cg.shared.global [%0], [%1], 16, %2;"
                 :: "r"(smem), "l"(gmem), "r"(szbytes));
}

// ---------------------------------------------------------------
// degree count
// ---------------------------------------------------------------
__global__ void k_deg_count(const int* __restrict__ dst, int E) {
    int i = blockIdx.x * blockDim.x + threadIdx.x;
    if (i >= E) return;
    int d = dst[i];
    if ((unsigned)d < NN) atomicAdd(&g_cnt[d], 1);
}

// weight pre-round to tf32 (both weights in one launch)
__global__ void k_cvt2(const float* __restrict__ W1, const float* __restrict__ W2) {
    int i = blockIdx.x * blockDim.x + threadIdx.x;
    if (i < D1 * D2)                 g_W1t[i]            = f2tf32(W1[i]);
    else if (i < 2 * D1 * D2)        g_W2t[i - D1 * D2]  = f2tf32(W2[i - D1 * D2]);
}

// ---------------------------------------------------------------
// exclusive scan of g_cnt -> g_off (+ dinv folded in)
// ---------------------------------------------------------------
__global__ __launch_bounds__(1024) void k_scan1() {
    __shared__ int sh[1024];
    int t   = threadIdx.x;
    int idx = blockIdx.x * 1024 + t;
    int v   = (idx < NN) ? g_cnt[idx] : 0;
    if (idx < NN) g_dinv[idx] = rsqrtf((float)(v + 1));   // +1 self loop
    sh[t] = v;
    __syncthreads();
    #pragma unroll
    for (int off = 1; off < 1024; off <<= 1) {
        int add = (t >= off) ? sh[t - off] : 0;
        __syncthreads();
        sh[t] += add;
        __syncthreads();
    }
    if (idx < NN) g_off[idx] = sh[t] - v;          // exclusive within chunk
    if (t == 1023) g_csum[blockIdx.x] = sh[1023];  // chunk total
}

__global__ void k_scan2() {
    if (threadIdx.x == 0) {
        int run = 0;
        for (int i = 0; i < NCHUNK; i++) { int c = g_csum[i]; g_csum[i] = run; run += c; }
        g_off[NN] = run;
    }
}

__global__ void k_scan3() {
    int i = blockIdx.x * blockDim.x + threadIdx.x;
    if (i < NN) {
        g_off[i] += g_csum[i >> 10];
        g_cursor[i] = 0;
    }
}

// ---------------------------------------------------------------
// CSR placement: bucket edges by dst
// ---------------------------------------------------------------
__global__ void k_place(const int* __restrict__ srcIdx,
                        const int* __restrict__ dstIdx, int E) {
    int e = blockIdx.x * blockDim.x + threadIdx.x;
    if (e >= E) return;
    int s = srcIdx[e], d = dstIdx[e];
    if ((unsigned)s >= NN || (unsigned)d >= NN) return;
    int pos = g_off[d] + atomicAdd(&g_cursor[d], 1);
    g_csr[pos] = s;
}

// ---------------------------------------------------------------
// CSR gather: out[n,:] = dinv[n]^2*feat[n,:] + sum_e dinv[n]dinv[s]*feat[s,:]
// one warp per node; lane owns 4 dims (float4). 4x unrolled edge loop (MLP).
// CVT: round output to tf32 (when it feeds a GEMM A operand).
// ---------------------------------------------------------------
template<bool RELU, bool BIAS, bool CVT>
__global__ __launch_bounds__(256)
void k_gather(const float* __restrict__ feat, float* __restrict__ out,
              const float* __restrict__ bias) {
    int gtid = blockIdx.x * blockDim.x + threadIdx.x;
    int n    = gtid >> 5;
    int lane = gtid & 31;
    if (n >= NN) return;

    float dn = g_dinv[n];
    float4 acc = ((const float4*)(feat + (size_t)n * D1))[lane];
    float w0 = dn * dn;
    acc.x *= w0; acc.y *= w0; acc.z *= w0; acc.w *= w0;

    int e   = g_off[n];
    int end = g_off[n + 1];
    for (; e + 3 < end; e += 4) {
        int s0 = g_csr[e];
        int s1 = g_csr[e + 1];
        int s2 = g_csr[e + 2];
        int s3 = g_csr[e + 3];
        float wA = dn * g_dinv[s0];
        float wB = dn * g_dinv[s1];
        float wC = dn * g_dinv[s2];
        float wD = dn * g_dinv[s3];
        float4 v0 = ((const float4*)(feat + (size_t)s0 * D1))[lane];
        float4 v1 = ((const float4*)(feat + (size_t)s1 * D1))[lane];
        float4 v2 = ((const float4*)(feat + (size_t)s2 * D1))[lane];
        float4 v3 = ((const float4*)(feat + (size_t)s3 * D1))[lane];
        acc.x += wA * v0.x + wB * v1.x + wC * v2.x + wD * v3.x;
        acc.y += wA * v0.y + wB * v1.y + wC * v2.y + wD * v3.y;
        acc.z += wA * v0.z + wB * v1.z + wC * v2.z + wD * v3.z;
        acc.w += wA * v0.w + wB * v1.w + wC * v2.w + wD * v3.w;
    }
    for (; e < end; e++) {
        int s = g_csr[e];
        float w = dn * g_dinv[s];
        float4 v = ((const float4*)(feat + (size_t)s * D1))[lane];
        acc.x += w * v.x; acc.y += w * v.y; acc.z += w * v.z; acc.w += w * v.w;
    }

    if (BIAS) {
        float4 b = *(const float4*)(bias + lane * 4);
        acc.x += b.x; acc.y += b.y; acc.z += b.z; acc.w += b.w;
    }
    if (RELU) {
        acc.x = fmaxf(acc.x, 0.f); acc.y = fmaxf(acc.y, 0.f);
        acc.z = fmaxf(acc.z, 0.f); acc.w = fmaxf(acc.w, 0.f);
    }
    if (CVT) {
        acc.x = f2tf32(acc.x); acc.y = f2tf32(acc.y);
        acc.z = f2tf32(acc.z); acc.w = f2tf32(acc.w);
    }
    ((float4*)(out + (size_t)n * D1))[lane] = acc;
}

// ---------------------------------------------------------------
// TF32 tensor-core GEMM, 2-stage cp.async pipeline, dynamic smem.
// Templated tile: BM x BN, BK=32, 256 threads (8 warps), warp tile 32x64.
// WC = BN/64 warp-columns, WR = 8/WC warp-rows; BM must equal WR*32.
// Inputs pre-rounded to tf32; smem fill is a raw cp.async copy.
// ---------------------------------------------------------------
__device__ __forceinline__ void mma_tf32(float* d, const unsigned* a, const unsigned* b) {
    asm volatile(
        "mma.sync.aligned.m16n8k8.row.col.f32.tf32.tf32.f32 "
        "{%0,%1,%2,%3}, {%4,%5,%6,%7}, {%8,%9}, {%0,%1,%2,%3};"
        : "+f"(d[0]), "+f"(d[1]), "+f"(d[2]), "+f"(d[3])
        : "r"(a[0]), "r"(a[1]), "r"(a[2]), "r"(a[3]), "r"(b[0]), "r"(b[1]));
}

#define GBK  32
#define APAD 36                          // pad kills stride-32 conflicts

template<int BM, int BN>
struct GemmSmem {
    static constexpr int BPAD    = BN + 4;
    static constexpr int A_STAGE = BM * APAD;
    static constexpr int B_STAGE = GBK * BPAD;
    static constexpr int BYTES   = (2 * A_STAGE + 2 * B_STAGE) * 4;
};

template<int BM, int BN, bool RELU, bool BIAS, bool CVT_OUT>
__global__ __launch_bounds__(256)
void gemm_tf32(const float* __restrict__ A, const float* __restrict__ B,
               const float* __restrict__ bias, float* __restrict__ C,
               int M, int N, int K)
{
    constexpr int BPAD    = GemmSmem<BM, BN>::BPAD;
    constexpr int A_STAGE = GemmSmem<BM, BN>::A_STAGE;
    constexpr int B_STAGE = GemmSmem<BM, BN>::B_STAGE;
    constexpr int WC      = BN / 64;      // warp columns
    constexpr int NB4     = BN / 4;       // float4 per B row

    extern __shared__ float smem[];
    float* As[2] = { smem,                smem + A_STAGE };
    float* Bs[2] = { smem + 2 * A_STAGE,  smem + 2 * A_STAGE + B_STAGE };

    const int tid  = threadIdx.x;
    const int lane = tid & 31;
    const int wid  = tid >> 5;
    const int wr   = wid / WC;     // warp row (32 M-rows each)
    const int wc   = wid % WC;     // warp col (64 N-cols each)
    const int bm   = blockIdx.y * BM;
    const int bn   = blockIdx.x * BN;

    float acc[2][8][4];
    #pragma unroll
    for (int i = 0; i < 2; i++)
        #pragma unroll
        for (int j = 0; j < 8; j++)
            #pragma unroll
            for (int q = 0; q < 4; q++) acc[i][j][q] = 0.f;

    // load mappings
    const int a_r = tid >> 3;            // + p*32, p < BM/32
    const int a_c = (tid & 7) * 4;
    const int b_r = tid / NB4;           // + p*(256/NB4), p < BN/32
    const int b_c = (tid % NB4) * 4;

    auto load_tile = [&](int k0, int st) {
        #pragma unroll
        for (int p = 0; p < BM / 32; p++) {
            int r = a_r + p * 32;
            int am = bm + r;
            uint32_t dstA = (uint32_t)__cvta_generic_to_shared(&As[st][r * APAD + a_c]);
            cp_async16(dstA, A + (size_t)am * K + k0 + a_c, (am < M) ? 16 : 0);
        }
        #pragma unroll
        for (int p = 0; p < BN / 32; p++) {
            int r = b_r + p * (256 / NB4);
            uint32_t dstB = (uint32_t)__cvta_generic_to_shared(&Bs[st][r * BPAD + b_c]);
            cp_async16(dstB, B + (size_t)(k0 + r) * N + bn + b_c, 16);
        }
    };

    const int ntile = K / GBK;
    load_tile(0, 0);
    asm volatile("cp.async.commit_group;");

    for (int t = 0; t < ntile; t++) {
        if (t + 1 < ntile) {
            load_tile((t + 1) * GBK, (t + 1) & 1);
            asm volatile("cp.async.commit_group;");
            asm volatile("cp.async.wait_group 1;");
        } else {
            asm volatile("cp.async.wait_group 0;");
        }
        __syncthreads();

        const float* Ast = As[t & 1];
        const float* Bst = Bs[t & 1];
        const int g  = lane >> 2;
        const int t4 = lane & 3;
        #pragma unroll
        for (int kk = 0; kk < GBK; kk += 8) {
            unsigned a[2][4];
            #pragma unroll
            for (int mt = 0; mt < 2; mt++) {
                int rb = wr * 32 + mt * 16 + g;
                a[mt][0] = __float_as_uint(Ast[(rb    ) * APAD + kk + t4    ]);
                a[mt][1] = __float_as_uint(Ast[(rb + 8) * APAD + kk + t4    ]);
                a[mt][2] = __float_as_uint(Ast[(rb    ) * APAD + kk + t4 + 4]);
                a[mt][3] = __float_as_uint(Ast[(rb + 8) * APAD + kk + t4 + 4]);
            }
            unsigned b[8][2];
            #pragma unroll
            for (int nt = 0; nt < 8; nt++) {
                int nb = wc * 64 + nt * 8 + g;
                b[nt][0] = __float_as_uint(Bst[(kk + t4    ) * BPAD + nb]);
                b[nt][1] = __float_as_uint(Bst[(kk + t4 + 4) * BPAD + nb]);
            }
            #pragma unroll
            for (int mt = 0; mt < 2; mt++)
                #pragma unroll
                for (int nt = 0; nt < 8; nt++)
                    mma_tf32(acc[mt][nt], a[mt], b[nt]);
        }
        __syncthreads();
    }

    // epilogue
    const int g  = lane >> 2;
    const int t4 = lane & 3;
    #pragma unroll
    for (int mt = 0; mt < 2; mt++) {
        #pragma unroll
        for (int nt = 0; nt < 8; nt++) {
            int col = bn + wc * 64 + nt * 8 + 2 * t4;
            float bx = 0.f, by = 0.f;
            if (BIAS) { bx = bias[col]; by = bias[col + 1]; }
            int r0 = bm + wr * 32 + mt * 16 + g;
            if (r0 < M) {
                float2 v;
                v.x = acc[mt][nt][0] + bx;
                v.y = acc[mt][nt][1] + by;
                if (RELU) { v.x = fmaxf(v.x, 0.f); v.y = fmaxf(v.y, 0.f); }
                if (CVT_OUT) { v.x = f2tf32(v.x); v.y = f2tf32(v.y); }
                *(float2*)(C + (size_t)r0 * N + col) = v;
            }
            int r1 = r0 + 8;
            if (r1 < M) {
                float2 v;
                v.x = acc[mt][nt][2] + bx;
                v.y = acc[mt][nt][3] + by;
                if (RELU) { v.x = fmaxf(v.x, 0.f); v.y = fmaxf(v.y, 0.f); }
                if (CVT_OUT) { v.x = f2tf32(v.x); v.y = f2tf32(v.y); }
                *(float2*)(C + (size_t)r1 * N + col) = v;
            }
        }
    }
}

// ---------------------------------------------------------------
// launch
// ---------------------------------------------------------------
extern "C" void kernel_launch(void* const* d_in, const int* in_sizes, int n_in,
                              void* d_out, int out_size)
{
    const float* x   = (const float*)d_in[0];
    const int*   ei  = (const int*)d_in[1];      // int32 (JAX x64 disabled)
    const float* W1  = (const float*)d_in[2];
    const float* b1  = (const float*)d_in[3];
    const float* W2  = (const float*)d_in[4];
    const float* b2  = (const float*)d_in[5];
    float*       out = (float*)d_out;

    const int E = in_sizes[1] / 2;
    const int* srcIdx = ei;
    const int* dstIdx = ei + E;

    float* bufA = nullptr;  cudaGetSymbolAddress((void**)&bufA, g_bufA);
    float* bufB = nullptr;  cudaGetSymbolAddress((void**)&bufB, g_bufB);
    float* W1t  = nullptr;  cudaGetSymbolAddress((void**)&W1t, g_W1t);
    float* W2t  = nullptr;  cudaGetSymbolAddress((void**)&W2t, g_W2t);
    int*   cnt  = nullptr;  cudaGetSymbolAddress((void**)&cnt, g_cnt);

    constexpr int SM1 = GemmSmem<64, 256>::BYTES;   // GEMM1: 64x256 tile
    constexpr int SM2 = GemmSmem<128, 128>::BYTES;  // GEMM2: 128x128 tile

    // raise dynamic smem caps (host attr set; graph-capture-safe, idempotent)
    cudaFuncSetAttribute(gemm_tf32<64, 256, true, true, true>,
                         cudaFuncAttributeMaxDynamicSharedMemorySize, SM1);
    cudaFuncSetAttribute(gemm_tf32<128, 128, false, false, false>,
                         cudaFuncAttributeMaxDynamicSharedMemorySize, SM2);

    const int T = 256;

    // 0) weight pre-round (single launch)
    k_cvt2<<<(2 * D1 * D2 + T - 1) / T, T>>>(W1, W2);

    // 1) degree + dinv + CSR build
    cudaMemsetAsync(cnt, 0, NN * sizeof(int));
    k_deg_count<<<(E + T - 1) / T, T>>>(dstIdx, E);
    k_scan1<<<NCHUNK, 1024>>>();                    // scan + dinv fused
    k_scan2<<<1, 32>>>();
    k_scan3<<<(NN + T - 1) / T, T>>>();
    k_place<<<(E + T - 1) / T, T>>>(srcIdx, dstIdx, E);

    // 2) layer-1 aggregation (gather, tf32-rounded out): bufA = A_norm @ x
    const int gthreads = NN * 32;
    k_gather<false, false, true><<<(gthreads + T - 1) / T, T>>>(x, bufA, nullptr);

    // 3) out1 = relu(bufA @ W1 + b1) -> bufB [N, 256] (tf32-rounded); A read once
    {
        dim3 grid(D2 / 256, (NN + 63) / 64);
        gemm_tf32<64, 256, true, true, true><<<grid, 256, SM1>>>(bufA, W1t, b1, bufB, NN, D2, D1);
    }

    // 4) h2 = bufB @ W2 -> bufA [N, 128] (full f32)
    {
        dim3 grid(D1 / 128, (NN + 127) / 128);
        gemm_tf32<128, 128, false, false, false><<<grid, 256, SM2>>>(bufB, W2t, nullptr, bufA, NN, D1, D2);
    }

    // 5) layer-2 aggregation (gather) + bias + relu -> out
    k_gather<true, true, false><<<(gthreads + T - 1) / T, T>>>(bufA, out, b2);
}

// round 14
// speedup vs baseline: 1.0443x; 1.0443x over previous
#include <cuda_runtime.h>
#include <cuda_bf16.h>
#include <cstddef>
#include <cstdint>

#define NN    100000        // nodes
#define D1    128           // input / layer-2 output dim
#define D2    256           // hidden dim
#define EMAX  700000        // max edges (setup uses 600k)
#define NCHUNK ((NN + 1023) / 1024)

// -------- scratch (no allocation allowed; __device__ globals) --------
__device__ int   g_cnt[NN];             // in-edge counts (no self loop)
__device__ float g_dinv[NN];
__device__ int   g_off[NN + 1];         // CSR row offsets
__device__ int   g_cursor[NN];          // placement cursors
__device__ int   g_csum[NCHUNK];        // chunk sums for scan
__device__ int   g_csr[EMAX];           // CSR column (src) indices
__device__ float g_bufA[(size_t)NN * D1];   // agg1 (tf32-rounded), later h2 (f32)
__device__ float g_bufB[(size_t)NN * D2];   // out1 (post relu, tf32-rounded)
__device__ float g_W1t[D1 * D2];            // tf32-rounded weights
__device__ float g_W2t[D2 * D1];

__device__ __forceinline__ float f2tf32(float x) {
    unsigned u;
    asm("cvt.rna.tf32.f32 %0, %1;" : "=r"(u) : "f"(x));
    return __uint_as_float(u);
}

__device__ __forceinline__ void cp_async16(uint32_t smem, const void* gmem, int szbytes) {
    asm volatile("cp.async.cg.shared.global [%0], [%1], 16, %2;"
                 :: "r"(smem), "l"(gmem), "r"(szbytes));
}

// ---------------------------------------------------------------
// degree count
// ---------------------------------------------------------------
__global__ void k_deg_count(const int* __restrict__ dst, int E) {
    int i = blockIdx.x * blockDim.x + threadIdx.x;
    if (i >= E) return;
    int d = dst[i];
    if ((unsigned)d < NN) atomicAdd(&g_cnt[d], 1);
}

// weight pre-round to tf32 (both weights in one launch)
__global__ void k_cvt2(const float* __restrict__ W1, const float* __restrict__ W2) {
    int i = blockIdx.x * blockDim.x + threadIdx.x;
    if (i < D1 * D2)                 g_W1t[i]            = f2tf32(W1[i]);
    else if (i < 2 * D1 * D2)        g_W2t[i - D1 * D2]  = f2tf32(W2[i - D1 * D2]);
}

// ---------------------------------------------------------------
// scan phase 1: per-chunk exclusive scan of g_cnt -> g_off (+ dinv folded in)
// ---------------------------------------------------------------
__global__ __launch_bounds__(1024) void k_scan1() {
    __shared__ int sh[1024];
    int t   = threadIdx.x;
    int idx = blockIdx.x * 1024 + t;
    int v   = (idx < NN) ? g_cnt[idx] : 0;
    if (idx < NN) g_dinv[idx] = rsqrtf((float)(v + 1));   // +1 self loop
    sh[t] = v;
    __syncthreads();
    #pragma unroll
    for (int off = 1; off < 1024; off <<= 1) {
        int add = (t >= off) ? sh[t - off] : 0;
        __syncthreads();
        sh[t] += add;
        __syncthreads();
    }
    if (idx < NN) g_off[idx] = sh[t] - v;          // exclusive within chunk
    if (t == 1023) g_csum[blockIdx.x] = sh[1023];  // chunk total
}

// ---------------------------------------------------------------
// scan phase 2 (parallel fixup): each block computes its chunk-prefix by a
// shared-memory tree reduce of csum[j < bid] (one LDG round, no serial chain),
// adds it to its g_off entries, zeroes cursors. Last block writes g_off[NN].
// ---------------------------------------------------------------
__global__ __launch_bounds__(1024) void k_scan_fix() {
    __shared__ int sh[128];
    const int bid = blockIdx.x;
    const int t   = threadIdx.x;

    if (t < 128) sh[t] = (t < NCHUNK && t < bid) ? g_csum[t] : 0;
    __syncthreads();
    #pragma unroll
    for (int s = 64; s > 0; s >>= 1) {
        if (t < s) sh[t] += sh[t + s];
        __syncthreads();
    }
    const int prefix = sh[0];

    int idx = bid * 1024 + t;
    if (idx < NN) {
        g_off[idx] += prefix;
        g_cursor[idx] = 0;
    }
    if (bid == gridDim.x - 1 && t == 0)
        g_off[NN] = prefix + g_csum[bid];          // total valid edges
}

// ---------------------------------------------------------------
// CSR placement: bucket edges by dst
// ---------------------------------------------------------------
__global__ void k_place(const int* __restrict__ srcIdx,
                        const int* __restrict__ dstIdx, int E) {
    int e = blockIdx.x * blockDim.x + threadIdx.x;
    if (e >= E) return;
    int s = srcIdx[e], d = dstIdx[e];
    if ((unsigned)s >= NN || (unsigned)d >= NN) return;
    int pos = g_off[d] + atomicAdd(&g_cursor[d], 1);
    g_csr[pos] = s;
}

// ---------------------------------------------------------------
// CSR gather: out[n,:] = dinv[n]^2*feat[n,:] + sum_e dinv[n]dinv[s]*feat[s,:]
// one warp per node; lane owns 4 dims (float4). 4x unrolled edge loop (MLP).
// CVT: round output to tf32 (when it feeds a GEMM A operand).
// ---------------------------------------------------------------
template<bool RELU, bool BIAS, bool CVT>
__global__ __launch_bounds__(256)
void k_gather(const float* __restrict__ feat, float* __restrict__ out,
              const float* __restrict__ bias) {
    int gtid = blockIdx.x * blockDim.x + threadIdx.x;
    int n    = gtid >> 5;
    int lane = gtid & 31;
    if (n >= NN) return;

    float dn = g_dinv[n];
    float4 acc = ((const float4*)(feat + (size_t)n * D1))[lane];
    float w0 = dn * dn;
    acc.x *= w0; acc.y *= w0; acc.z *= w0; acc.w *= w0;

    int e   = g_off[n];
    int end = g_off[n + 1];
    for (; e + 3 < end; e += 4) {
        int s0 = g_csr[e];
        int s1 = g_csr[e + 1];
        int s2 = g_csr[e + 2];
        int s3 = g_csr[e + 3];
        float wA = dn * g_dinv[s0];
        float wB = dn * g_dinv[s1];
        float wC = dn * g_dinv[s2];
        float wD = dn * g_dinv[s3];
        float4 v0 = ((const float4*)(feat + (size_t)s0 * D1))[lane];
        float4 v1 = ((const float4*)(feat + (size_t)s1 * D1))[lane];
        float4 v2 = ((const float4*)(feat + (size_t)s2 * D1))[lane];
        float4 v3 = ((const float4*)(feat + (size_t)s3 * D1))[lane];
        acc.x += wA * v0.x + wB * v1.x + wC * v2.x + wD * v3.x;
        acc.y += wA * v0.y + wB * v1.y + wC * v2.y + wD * v3.y;
        acc.z += wA * v0.z + wB * v1.z + wC * v2.z + wD * v3.z;
        acc.w += wA * v0.w + wB * v1.w + wC * v2.w + wD * v3.w;
    }
    for (; e < end; e++) {
        int s = g_csr[e];
        float w = dn * g_dinv[s];
        float4 v = ((const float4*)(feat + (size_t)s * D1))[lane];
        acc.x += w * v.x; acc.y += w * v.y; acc.z += w * v.z; acc.w += w * v.w;
    }

    if (BIAS) {
        float4 b = *(const float4*)(bias + lane * 4);
        acc.x += b.x; acc.y += b.y; acc.z += b.z; acc.w += b.w;
    }
    if (RELU) {
        acc.x = fmaxf(acc.x, 0.f); acc.y = fmaxf(acc.y, 0.f);
        acc.z = fmaxf(acc.z, 0.f); acc.w = fmaxf(acc.w, 0.f);
    }
    if (CVT) {
        acc.x = f2tf32(acc.x); acc.y = f2tf32(acc.y);
        acc.z = f2tf32(acc.z); acc.w = f2tf32(acc.w);
    }
    ((float4*)(out + (size_t)n * D1))[lane] = acc;
}

// ---------------------------------------------------------------
// TF32 tensor-core GEMM, 2-stage cp.async pipeline, dynamic smem.
// CTA tile 128x128, BK=32, 256 threads (8 warps), warp tile 32x64.
// Inputs pre-rounded to tf32; smem fill is a raw cp.async copy.
// CVT_OUT rounds the f32 result to tf32 (when C feeds the next GEMM).
// ---------------------------------------------------------------
__device__ __forceinline__ void mma_tf32(float* d, const unsigned* a, const unsigned* b) {
    asm volatile(
        "mma.sync.aligned.m16n8k8.row.col.f32.tf32.tf32.f32 "
        "{%0,%1,%2,%3}, {%4,%5,%6,%7}, {%8,%9}, {%0,%1,%2,%3};"
        : "+f"(d[0]), "+f"(d[1]), "+f"(d[2]), "+f"(d[3])
        : "r"(a[0]), "r"(a[1]), "r"(a[2]), "r"(a[3]), "r"(b[0]), "r"(b[1]));
}

#define GBM 128
#define GBN 128
#define GBK 32
#define APAD 36                         // pad kills stride-32 conflicts
#define BPAD 132
#define A_STAGE (GBM * APAD)            // 4608 floats per stage
#define B_STAGE (GBK * BPAD)            // 4224 floats per stage
#define GEMM_SMEM_BYTES  ((2 * A_STAGE + 2 * B_STAGE) * 4)   // 70656 bytes

template<bool RELU, bool BIAS, bool CVT_OUT>
__global__ __launch_bounds__(256)
void gemm_tf32(const float* __restrict__ A, const float* __restrict__ B,
               const float* __restrict__ bias, float* __restrict__ C,
               int M, int N, int K)
{
    extern __shared__ float smem[];
    float* As[2] = { smem,                smem + A_STAGE };
    float* Bs[2] = { smem + 2 * A_STAGE,  smem + 2 * A_STAGE + B_STAGE };

    const int tid  = threadIdx.x;
    const int lane = tid & 31;
    const int wid  = tid >> 5;
    const int wr   = wid >> 1;     // warp row 0..3 (32 M-rows each)
    const int wc   = wid & 1;      // warp col 0..1 (64 N-cols each)
    const int bm   = blockIdx.y * GBM;
    const int bn   = blockIdx.x * GBN;

    float acc[2][8][4];
    #pragma unroll
    for (int i = 0; i < 2; i++)
        #pragma unroll
        for (int j = 0; j < 8; j++)
            #pragma unroll
            for (int q = 0; q < 4; q++) acc[i][j][q] = 0.f;

    // load mappings
    const int a_r = tid >> 3;          // + p*32
    const int a_c = (tid & 7) * 4;
    const int b_r = tid >> 5;          // + p*8
    const int b_c = (tid & 31) * 4;

    auto load_tile = [&](int k0, int st) {
        #pragma unroll
        for (int p = 0; p < 4; p++) {
            int r = a_r + p * 32;
            int am = bm + r;
            uint32_t dstA = (uint32_t)__cvta_generic_to_shared(&As[st][r * APAD + a_c]);
            cp_async16(dstA, A + (size_t)am * K + k0 + a_c, (am < M) ? 16 : 0);
        }
        #pragma unroll
        for (int p = 0; p < 4; p++) {
            int r = b_r + p * 8;
            uint32_t dstB = (uint32_t)__cvta_generic_to_shared(&Bs[st][r * BPAD + b_c]);
            cp_async16(dstB, B + (size_t)(k0 + r) * N + bn + b_c, 16);
        }
    };

    const int ntile = K / GBK;
    load_tile(0, 0);
    asm volatile("cp.async.commit_group;");

    for (int t = 0; t < ntile; t++) {
        if (t + 1 < ntile) {
            load_tile((t + 1) * GBK, (t + 1) & 1);
            asm volatile("cp.async.commit_group;");
            asm volatile("cp.async.wait_group 1;");
        } else {
            asm volatile("cp.async.wait_group 0;");
        }
        __syncthreads();

        const float* Ast = As[t & 1];
        const float* Bst = Bs[t & 1];
        const int g  = lane >> 2;
        const int t4 = lane & 3;
        #pragma unroll
        for (int kk = 0; kk < GBK; kk += 8) {
            unsigned a[2][4];
            #pragma unroll
            for (int mt = 0; mt < 2; mt++) {
                int rb = wr * 32 + mt * 16 + g;
                a[mt][0] = __float_as_uint(Ast[(rb    ) * APAD + kk + t4    ]);
                a[mt][1] = __float_as_uint(Ast[(rb + 8) * APAD + kk + t4    ]);
                a[mt][2] = __float_as_uint(Ast[(rb    ) * APAD + kk + t4 + 4]);
                a[mt][3] = __float_as_uint(Ast[(rb + 8) * APAD + kk + t4 + 4]);
            }
            unsigned b[8][2];
            #pragma unroll
            for (int nt = 0; nt < 8; nt++) {
                int nb = wc * 64 + nt * 8 + g;
                b[nt][0] = __float_as_uint(Bst[(kk + t4    ) * BPAD + nb]);
                b[nt][1] = __float_as_uint(Bst[(kk + t4 + 4) * BPAD + nb]);
            }
            #pragma unroll
            for (int mt = 0; mt < 2; mt++)
                #pragma unroll
                for (int nt = 0; nt < 8; nt++)
                    mma_tf32(acc[mt][nt], a[mt], b[nt]);
        }
        __syncthreads();
    }

    // epilogue
    const int g  = lane >> 2;
    const int t4 = lane & 3;
    #pragma unroll
    for (int mt = 0; mt < 2; mt++) {
        #pragma unroll
        for (int nt = 0; nt < 8; nt++) {
            int col = bn + wc * 64 + nt * 8 + 2 * t4;
            float bx = 0.f, by = 0.f;
            if (BIAS) { bx = bias[col]; by = bias[col + 1]; }
            int r0 = bm + wr * 32 + mt * 16 + g;
            if (r0 < M) {
                float2 v;
                v.x = acc[mt][nt][0] + bx;
                v.y = acc[mt][nt][1] + by;
                if (RELU) { v.x = fmaxf(v.x, 0.f); v.y = fmaxf(v.y, 0.f); }
                if (CVT_OUT) { v.x = f2tf32(v.x); v.y = f2tf32(v.y); }
                *(float2*)(C + (size_t)r0 * N + col) = v;
            }
            int r1 = r0 + 8;
            if (r1 < M) {
                float2 v;
                v.x = acc[mt][nt][2] + bx;
                v.y = acc[mt][nt][3] + by;
                if (RELU) { v.x = fmaxf(v.x, 0.f); v.y = fmaxf(v.y, 0.f); }
                if (CVT_OUT) { v.x = f2tf32(v.x); v.y = f2tf32(v.y); }
                *(float2*)(C + (size_t)r1 * N + col) = v;
            }
        }
    }
}

// ---------------------------------------------------------------
// launch
// ---------------------------------------------------------------
extern "C" void kernel_launch(void* const* d_in, const int* in_sizes, int n_in,
                              void* d_out, int out_size)
{
    const float* x   = (const float*)d_in[0];
    const int*   ei  = (const int*)d_in[1];      // int32 (JAX x64 disabled)
    const float* W1  = (const float*)d_in[2];
    const float* b1  = (const float*)d_in[3];
    const float* W2  = (const float*)d_in[4];
    const float* b2  = (const float*)d_in[5];
    float*       out = (float*)d_out;

    const int E = in_sizes[1] / 2;
    const int* srcIdx = ei;
    const int* dstIdx = ei + E;

    float* bufA = nullptr;  cudaGetSymbolAddress((void**)&bufA, g_bufA);
    float* bufB = nullptr;  cudaGetSymbolAddress((void**)&bufB, g_bufB);
    float* W1t  = nullptr;  cudaGetSymbolAddress((void**)&W1t, g_W1t);
    float* W2t  = nullptr;  cudaGetSymbolAddress((void**)&W2t, g_W2t);
    int*   cnt  = nullptr;  cudaGetSymbolAddress((void**)&cnt, g_cnt);

    // raise dynamic smem caps (host attr set; graph-capture-safe, idempotent)
    cudaFuncSetAttribute(gemm_tf32<true, true, true>,
                         cudaFuncAttributeMaxDynamicSharedMemorySize, GEMM_SMEM_BYTES);
    cudaFuncSetAttribute(gemm_tf32<false, false, false>,
                         cudaFuncAttributeMaxDynamicSharedMemorySize, GEMM_SMEM_BYTES);

    const int T = 256;

    // 0) weight pre-round (single launch)
    k_cvt2<<<(2 * D1 * D2 + T - 1) / T, T>>>(W1, W2);

    // 1) degree + dinv + CSR build
    cudaMemsetAsync(cnt, 0, NN * sizeof(int));
    k_deg_count<<<(E + T - 1) / T, T>>>(dstIdx, E);
    k_scan1<<<NCHUNK, 1024>>>();                    // scan + dinv fused
    k_scan_fix<<<NCHUNK, 1024>>>();                 // parallel prefix fixup
    k_place<<<(E + T - 1) / T, T>>>(srcIdx, dstIdx, E);

    // 2) layer-1 aggregation (gather, tf32-rounded out): bufA = A_norm @ x
    const int gthreads = NN * 32;
    k_gather<false, false, true><<<(gthreads + T - 1) / T, T>>>(x, bufA, nullptr);

    // 3) out1 = relu(bufA @ W1 + b1) -> bufB [N, 256] (tf32-rounded)
    {
        dim3 grid(D2 / 128, (NN + 127) / 128);
        gemm_tf32<true, true, true><<<grid, 256, GEMM_SMEM_BYTES>>>(bufA, W1t, b1, bufB, NN, D2, D1);
    }

    // 4) h2 = bufB @ W2 -> bufA [N, 128] (full f32)
    {
        dim3 grid(D1 / 128, (NN + 127) / 128);
        gemm_tf32<false, false, false><<<grid, 256, GEMM_SMEM_BYTES>>>(bufB, W2t, nullptr, bufA, NN, D1, D2);
    }

    // 5) layer-2 aggregation (gather) + bias + relu -> out
    k_gather<true, true, false><<<(gthreads + T - 1) / T, T>>>(bufA, out, b2);
}